// round 8
// baseline (speedup 1.0000x reference)
#include <cuda_runtime.h>
#include <cuda_fp16.h>
#include <cstdint>

// ---------------- problem constants ----------------
#define N_NODES 100000
#define N_EDGES 3200000
#define F_IN    512
#define HEADS   8
#define HID     8
#define C1      64
#define NCLS    16
#define TOTE    (N_EDGES + N_NODES)
#define NB1024  ((N_NODES + 1023) / 1024)

// ---------------- device scratch ----------------
__device__ __half g_h1  [(size_t)N_NODES * C1];
__device__ float  g_hact[(size_t)N_NODES * C1];
__device__ float  g_as1 [(size_t)N_NODES * HEADS];
__device__ float  g_ad1 [(size_t)N_NODES * HEADS];
__device__ __half g_h2  [(size_t)N_NODES * NCLS];
__device__ float  g_as2 [N_NODES];
__device__ float  g_ad2 [N_NODES];
__device__ int    g_rowptr[N_NODES + 1];
__device__ int    g_cnt [N_NODES];
__device__ int    g_woff[N_NODES];
__device__ int    g_srcs[TOTE];
__device__ int    g_part [128];
__device__ int    g_part2[128];
__device__ int    g_is64;
__device__ unsigned g_gmax1[8];
__device__ unsigned g_gmax2;

// ---------------- helpers ----------------
__device__ __forceinline__ float leaky02(float x) { return fmaxf(x, 0.2f * x); }

__device__ __forceinline__ long long load_idx(const void* p, long long i, int is64) {
    return is64 ? ((const long long*)p)[i] : (long long)((const int*)p)[i];
}

__device__ __forceinline__ unsigned long long pack2(float x, float y) {
    unsigned long long r;
    asm("mov.b64 %0,{%1,%2};" : "=l"(r) : "f"(x), "f"(y));
    return r;
}
__device__ __forceinline__ void fma2(unsigned long long& d, unsigned long long a, unsigned long long b) {
    asm("fma.rn.f32x2 %0,%1,%2,%0;" : "+l"(d) : "l"(a), "l"(b));
}
__device__ __forceinline__ float2 unpack2(unsigned long long v) {
    float2 f;
    asm("mov.b64 {%0,%1},%2;" : "=f"(f.x), "=f"(f.y) : "l"(v));
    return f;
}
__device__ __forceinline__ unsigned fenc(float f) {
    unsigned u = __float_as_uint(f);
    return (u & 0x80000000u) ? ~u : (u | 0x80000000u);
}
__device__ __forceinline__ float fdec(unsigned u) {
    return __uint_as_float((u & 0x80000000u) ? (u & 0x7FFFFFFFu) : ~u);
}
#define ENC_NEG_INF 0x007FFFFFu

__device__ __forceinline__ uint32_t smem_u32(const void* p) {
    uint32_t a;
    asm("{ .reg .u64 t; cvta.to.shared.u64 t, %1; cvt.u32.u64 %0, t; }" : "=r"(a) : "l"(p));
    return a;
}
__device__ __forceinline__ void cpa16(uint32_t d, const float* s, int sz) {
    asm volatile("cp.async.ca.shared.global [%0], [%1], 16, %2;" :: "r"(d), "l"(s), "r"(sz));
}
__device__ __forceinline__ void cpa_commit() {
    asm volatile("cp.async.commit_group;");
}
template <int N>
__device__ __forceinline__ void cpa_wait() {
    asm volatile("cp.async.wait_group %0;" :: "n"(N));
}

// ---------------- dtype probe + per-call resets ----------------
__global__ void probe_k(const void* ei) {
    __shared__ int s_bad;
    if (threadIdx.x < 8)  g_gmax1[threadIdx.x] = ENC_NEG_INF;
    if (threadIdx.x == 8) g_gmax2 = ENC_NEG_INF;
    if (threadIdx.x == 0) s_bad = 0;
    __syncthreads();
    const long long* p = (const long long*)ei;
    for (int i = threadIdx.x; i < 1024; i += blockDim.x) {
        long long v = p[i];
        if ((v >> 32) != 0) s_bad = 1;
    }
    __syncthreads();
    if (threadIdx.x == 0) g_is64 = (s_bad == 0) ? 1 : 0;
}

// ---------------- GEMM1 (cp.async, f32x2-over-N, 3 CTA/SM) + fused attn + max ----------------
#define MT   128
#define BK   32
#define AST  36                 // A row stride in floats (144 B)
#define ABUF (MT * AST)         // 4608 floats / buffer
#define BBUF (BK * 64)          // 2048 floats / buffer
#define G1_SMEM ((2 * ABUF + 2 * BBUF) * 4)   // 53248 B

__device__ __forceinline__ void g1_stage(const float* __restrict__ X,
                                         const float* __restrict__ W,
                                         int m0, int kt, int buf,
                                         uint32_t aBase, uint32_t bBase, int tid) {
    const int k0 = kt * BK;
    // A: 128 rows x 128 B; 2 threads/row, 4 chunks each
    {
        const int row = tid >> 1;
        const int gm  = m0 + row;
        const int sz  = (gm < N_NODES) ? 16 : 0;
        const float* src = X + (size_t)((gm < N_NODES) ? gm : 0) * F_IN + k0 + (tid & 1) * 16;
        uint32_t dst = aBase + (uint32_t)(buf * ABUF + row * AST + (tid & 1) * 16) * 4u;
#pragma unroll
        for (int j = 0; j < 4; j++)
            cpa16(dst + j * 16u, src + j * 4, sz);
    }
    // B: 32 rows x 256 B = 512 chunks; 2/thread
    {
#pragma unroll
        for (int r = 0; r < 2; r++) {
            int idx = tid + r * 256;
            int row = idx >> 4, col = (idx & 15) * 4;
            cpa16(bBase + (uint32_t)(buf * BBUF + row * 64 + col) * 4u,
                  W + (size_t)(k0 + row) * 64 + col, 16);
        }
    }
    cpa_commit();
}

__global__ __launch_bounds__(256, 3) void gemm1_k(const float* __restrict__ X,
                                                  const float* __restrict__ W,
                                                  const float* __restrict__ asw,
                                                  const float* __restrict__ adw) {
    extern __shared__ float sm[];
    __shared__ unsigned sMax[8];
    const int tid = threadIdx.x;
    const int tx  = tid & 7;          // n group (head)
    const int ty  = tid >> 3;         // m group (4 rows)
    const int m0  = blockIdx.x * MT;
    if (tid < 8) sMax[tid] = ENC_NEG_INF;

    const uint32_t aBase = smem_u32(sm);
    const uint32_t bBase = smem_u32(sm + 2 * ABUF);

    unsigned long long acc[4][4];
#pragma unroll
    for (int i = 0; i < 4; i++)
#pragma unroll
        for (int jp = 0; jp < 4; jp++) acc[i][jp] = 0ull;

    g1_stage(X, W, m0, 0, 0, aBase, bBase, tid);

    const int NT = F_IN / BK;   // 16
    for (int kt = 0; kt < NT; kt++) {
        const int buf = kt & 1;
        if (kt + 1 < NT) {
            g1_stage(X, W, m0, kt + 1, buf ^ 1, aBase, bBase, tid);
            cpa_wait<1>();
        } else {
            cpa_wait<0>();
        }
        __syncthreads();

        const float* A = sm + buf * ABUF + (ty * 4) * AST;
        const float* B = sm + 2 * ABUF + buf * BBUF + tx * 8;
#pragma unroll
        for (int k4 = 0; k4 < 8; k4++) {
            float4 a0 = *(const float4*)(A + 0 * AST + k4 * 4);
            float4 a1 = *(const float4*)(A + 1 * AST + k4 * 4);
            float4 a2 = *(const float4*)(A + 2 * AST + k4 * 4);
            float4 a3 = *(const float4*)(A + 3 * AST + k4 * 4);
#pragma unroll
            for (int kk = 0; kk < 4; kk++) {
                const float* Bk = B + (k4 * 4 + kk) * 64;
                unsigned long long b0 = *(const unsigned long long*)(Bk + 0);
                unsigned long long b1 = *(const unsigned long long*)(Bk + 2);
                unsigned long long b2 = *(const unsigned long long*)(Bk + 4);
                unsigned long long b3 = *(const unsigned long long*)(Bk + 6);
                const float av[4] = {((const float*)&a0)[kk], ((const float*)&a1)[kk],
                                     ((const float*)&a2)[kk], ((const float*)&a3)[kk]};
#pragma unroll
                for (int i = 0; i < 4; i++) {
                    unsigned long long p = pack2(av[i], av[i]);
                    fma2(acc[i][0], p, b0);
                    fma2(acc[i][1], p, b1);
                    fma2(acc[i][2], p, b2);
                    fma2(acc[i][3], p, b3);
                }
            }
        }
        __syncthreads();
    }

    // epilogue: this thread owns head tx fully for rows m0+ty*4..+3
    float sa[8], da[8];
#pragma unroll
    for (int j = 0; j < 8; j++) {
        sa[j] = __ldg(asw + tx * 8 + j);
        da[j] = __ldg(adw + tx * 8 + j);
    }
    float lmax = -1e30f;
#pragma unroll
    for (int i = 0; i < 4; i++) {
        const int gm = m0 + ty * 4 + i;
        float o[8];
#pragma unroll
        for (int jp = 0; jp < 4; jp++) {
            float2 f = unpack2(acc[i][jp]);
            o[2 * jp]     = f.x;
            o[2 * jp + 1] = f.y;
        }
        if (gm < N_NODES) {
            union { __half2 h[4]; float4 f4; } u;
#pragma unroll
            for (int q = 0; q < 4; q++)
                u.h[q] = __floats2half2_rn(o[2 * q], o[2 * q + 1]);
            *(float4*)(g_h1 + (size_t)gm * C1 + tx * 8) = u.f4;
            float sv = 0.f, dv = 0.f;
#pragma unroll
            for (int j = 0; j < 8; j++) { sv += o[j] * sa[j]; dv += o[j] * da[j]; }
            g_as1[(size_t)gm * 8 + tx] = sv;
            g_ad1[(size_t)gm * 8 + tx] = dv;
            lmax = fmaxf(lmax, sv);
        }
    }
    __syncthreads();
    atomicMax(&sMax[tx], fenc(lmax));
    __syncthreads();
    if (tid < 8) atomicMax(&g_gmax1[tid], sMax[tid]);
}

// ---------------- CSR build ----------------
__global__ void initcnt_k() {
    int n = blockIdx.x * blockDim.x + threadIdx.x;
    if (n < N_NODES) g_cnt[n] = 1;
}

__global__ void count_k(const void* ei) {   // 2 edges per thread
    long long e = 2 * ((long long)blockIdx.x * blockDim.x + threadIdx.x);
    if (e >= N_EDGES) return;
    int d0, d1;
    if (g_is64) {
        longlong2 v = *(const longlong2*)((const long long*)ei + N_EDGES + e);
        d0 = (int)v.x; d1 = (int)v.y;
    } else {
        int2 v = *(const int2*)((const int*)ei + N_EDGES + e);
        d0 = v.x; d1 = v.y;
    }
    atomicAdd(&g_cnt[d0], 1);
    atomicAdd(&g_cnt[d1], 1);
}

__global__ void scan1_k() {
    __shared__ int ws[32];
    const int b = blockIdx.x, t = threadIdx.x;
    const int i = b * 1024 + t;
    int v = (i < N_NODES) ? g_cnt[i] : 0;
    const int lane = t & 31, w = t >> 5;
    int x = v;
#pragma unroll
    for (int o = 1; o < 32; o <<= 1) {
        int y = __shfl_up_sync(0xffffffffu, x, o);
        if (lane >= o) x += y;
    }
    if (lane == 31) ws[w] = x;
    __syncthreads();
    if (w == 0) {
        int y = ws[lane];
#pragma unroll
        for (int o = 1; o < 32; o <<= 1) {
            int z = __shfl_up_sync(0xffffffffu, y, o);
            if (lane >= o) y += z;
        }
        ws[lane] = y;
    }
    __syncthreads();
    int off  = (w > 0) ? ws[w - 1] : 0;
    int incl = x + off;
    if (i < N_NODES) g_rowptr[i] = incl - v;
    if (t == 1023) g_part[b] = incl;
}

__global__ void scan2_k() {
    __shared__ int buf[128];
    int t = threadIdx.x;
    buf[t] = (t < NB1024) ? g_part[t] : 0;
    __syncthreads();
#pragma unroll
    for (int o = 1; o < 128; o <<= 1) {
        int y = (t >= o) ? buf[t - o] : 0;
        __syncthreads();
        buf[t] += y;
        __syncthreads();
    }
    g_part2[t] = buf[t];
}

__global__ void scan3_selfloop_k() {
    int b = blockIdx.x, i = b * 1024 + threadIdx.x;
    if (i == 0) g_rowptr[N_NODES] = TOTE;
    if (i >= N_NODES) return;
    int off = (b > 0) ? g_part2[b - 1] : 0;
    int p = g_rowptr[i] + off;
    g_rowptr[i] = p;
    g_srcs[p]   = i;
    g_woff[i]   = p + 1;
}

__global__ void scatter_k(const void* ei) {   // 2 edges per thread
    long long e = 2 * ((long long)blockIdx.x * blockDim.x + threadIdx.x);
    if (e >= N_EDGES) return;
    int s0, s1, d0, d1;
    if (g_is64) {
        longlong2 sv = *(const longlong2*)((const long long*)ei + e);
        longlong2 dv = *(const longlong2*)((const long long*)ei + N_EDGES + e);
        s0 = (int)sv.x; s1 = (int)sv.y; d0 = (int)dv.x; d1 = (int)dv.y;
    } else {
        int2 sv = *(const int2*)((const int*)ei + e);
        int2 dv = *(const int2*)((const int*)ei + N_EDGES + e);
        s0 = sv.x; s1 = sv.y; d0 = dv.x; d1 = dv.y;
    }
    int p0 = atomicAdd(&g_woff[d0], 1);
    g_srcs[p0] = s0;
    int p1 = atomicAdd(&g_woff[d1], 1);
    g_srcs[p1] = s1;
}

// ---------------- layer1 aggregate: single pass, half-warp-per-edge gather ----------------
__global__ void agg1_k(const float* __restrict__ b1) {
    const int gw   = (blockIdx.x * blockDim.x + threadIdx.x) >> 5;
    const int lane = threadIdx.x & 31;
    const int w    = threadIdx.x >> 5;
    __shared__ float sAl [8][8][32];
    __shared__ int   sSrc[8][32];
    if (gw >= N_NODES) return;
    const int beg = g_rowptr[gw], end = g_rowptr[gw + 1];

    float ad[8], mh[8];
    {
        float4 u = *(const float4*)(g_ad1 + (size_t)gw * 8);
        float4 v = *(const float4*)(g_ad1 + (size_t)gw * 8 + 4);
        ad[0]=u.x; ad[1]=u.y; ad[2]=u.z; ad[3]=u.w;
        ad[4]=v.x; ad[5]=v.y; ad[6]=v.z; ad[7]=v.w;
    }
#pragma unroll
    for (int h = 0; h < 8; h++)
        mh[h] = leaky02(fdec(g_gmax1[h]) + ad[h]);

    const int eh  = lane >> 4;     // which edge of pair
    const int li  = lane & 15;
    const int c0  = li * 4;        // 4 fp16 channels
    const int hd2 = li >> 1;
    float ws[8];
#pragma unroll
    for (int h = 0; h < 8; h++) ws[h] = 0.f;
    float a0 = 0.f, a1 = 0.f, a2 = 0.f, a3 = 0.f;

    for (int chunk = beg; chunk < end; chunk += 32) {
        int i = chunk + lane;
        int sx = gw;
        float e8[8];
        if (i < end) {
            sx = g_srcs[i];
            float4 u = *(const float4*)(g_as1 + (size_t)sx * 8);
            float4 v = *(const float4*)(g_as1 + (size_t)sx * 8 + 4);
            float xs[8] = {u.x, u.y, u.z, u.w, v.x, v.y, v.z, v.w};
#pragma unroll
            for (int h = 0; h < 8; h++) {
                e8[h] = __expf(leaky02(xs[h] + ad[h]) - mh[h]);
                ws[h] += e8[h];
            }
        } else {
#pragma unroll
            for (int h = 0; h < 8; h++) e8[h] = 0.f;
        }
        sSrc[w][lane] = sx;
#pragma unroll
        for (int h = 0; h < 8; h++) sAl[w][h][lane] = e8[h];
        __syncwarp();

        const int ec = min(32, end - chunk);
        for (int e0 = 0; e0 < ec; e0 += 2) {
            const int edge = e0 + eh;          // may be == ec (alpha 0)
            const int   sy = sSrc[w][edge];
            const float al = sAl[w][hd2][edge];
            uint2 hv = *(const uint2*)(g_h1 + (size_t)sy * C1 + c0);
            float2 p0 = __half22float2(*(const __half2*)&hv.x);
            float2 p1 = __half22float2(*(const __half2*)&hv.y);
            a0 += p0.x * al; a1 += p0.y * al;
            a2 += p1.x * al; a3 += p1.y * al;
        }
        __syncwarp();
    }

#pragma unroll
    for (int o = 16; o; o >>= 1)
#pragma unroll
        for (int h = 0; h < 8; h++)
            ws[h] += __shfl_xor_sync(0xffffffffu, ws[h], o);

    a0 += __shfl_xor_sync(0xffffffffu, a0, 16);
    a1 += __shfl_xor_sync(0xffffffffu, a1, 16);
    a2 += __shfl_xor_sync(0xffffffffu, a2, 16);
    a3 += __shfl_xor_sync(0xffffffffu, a3, 16);

    if (lane < 16) {
        const float rsh = 1.0f / ws[hd2];
        float4 bb = *(const float4*)(b1 + c0);
        float o0 = a0 * rsh + bb.x;
        float o1 = a1 * rsh + bb.y;
        float o2 = a2 * rsh + bb.z;
        float o3 = a3 * rsh + bb.w;
        o0 = (o0 > 0.f) ? o0 : (__expf(o0) - 1.0f);
        o1 = (o1 > 0.f) ? o1 : (__expf(o1) - 1.0f);
        o2 = (o2 > 0.f) ? o2 : (__expf(o2) - 1.0f);
        o3 = (o3 > 0.f) ? o3 : (__expf(o3) - 1.0f);
        *(float4*)(g_hact + (size_t)gw * C1 + c0) = make_float4(o0, o1, o2, o3);
    }
}

// ---------------- layer2 GEMM + attn coefs + fused max ----------------
__global__ void gemm2_attn_k(const float* __restrict__ W2,
                             const float* __restrict__ asrc2,
                             const float* __restrict__ adst2) {
    __shared__ float Xs[16 * 64];
    __shared__ float Ws[64 * 16];
    __shared__ unsigned sM2;
    const int tid = threadIdx.x;
    const int n0  = blockIdx.x * 16;
    if (tid == 0) sM2 = ENC_NEG_INF;

    ((float4*)Ws)[tid] = ((const float4*)W2)[tid];
    {
        int row = tid >> 4;
        float4 v = make_float4(0.f, 0.f, 0.f, 0.f);
        if (n0 + row < N_NODES)
            v = ((const float4*)(g_hact + (size_t)n0 * C1))[tid];
        ((float4*)Xs)[tid] = v;
    }
    __syncthreads();

    const int r = tid >> 4, c = tid & 15;
    float acc = 0.f;
#pragma unroll
    for (int k = 0; k < 64; k++) acc += Xs[r * 64 + k] * Ws[k * 16 + c];
    const int n = n0 + r;
    if (n < N_NODES) g_h2[(size_t)n * NCLS + c] = __float2half_rn(acc);

    float vs = acc * asrc2[c];
    float vd = acc * adst2[c];
#pragma unroll
    for (int off = 8; off; off >>= 1) {
        vs += __shfl_xor_sync(0xffffffffu, vs, off);
        vd += __shfl_xor_sync(0xffffffffu, vd, off);
    }
    if (c == 0) {
        if (n < N_NODES) {
            g_as2[n] = vs;
            g_ad2[n] = vd;
            atomicMax(&sM2, fenc(vs));
        }
    }
    __syncthreads();
    if (tid == 0) atomicMax(&g_gmax2, sM2);
}

// ---------------- layer2 aggregate: single pass ----------------
__global__ void agg2_k(const float* __restrict__ b2, float* __restrict__ out) {
    const int gw   = (blockIdx.x * blockDim.x + threadIdx.x) >> 5;
    const int lane = threadIdx.x & 31;
    const int w    = threadIdx.x >> 5;
    __shared__ float sAl [8][32];
    __shared__ int   sSrc[8][32];
    if (gw >= N_NODES) return;
    const int beg = g_rowptr[gw], end = g_rowptr[gw + 1];
    const float adn = g_ad2[gw];
    const float mh  = leaky02(fdec(g_gmax2) + adn);

    const int c    = lane & 15;
    const int half = lane >> 4;
    float acc = 0.f, ws = 0.f;

    for (int chunk = beg; chunk < end; chunk += 32) {
        int i = chunk + lane;
        int sx = gw;
        float e = 0.f;
        if (i < end) {
            sx = g_srcs[i];
            e  = __expf(leaky02(g_as2[sx] + adn) - mh);
            ws += e;
        }
        sSrc[w][lane] = sx;
        sAl [w][lane] = e;
        __syncwarp();

        const int ec = min(32, end - chunk);
#pragma unroll 8
        for (int e0 = half; e0 < ec; e0 += 2) {
            int   sy = sSrc[w][e0];
            float al = sAl[w][e0];
            acc += __half2float(g_h2[(size_t)sy * NCLS + c]) * al;
        }
        __syncwarp();
    }

#pragma unroll
    for (int o = 16; o; o >>= 1)
        ws += __shfl_xor_sync(0xffffffffu, ws, o);
    const float rs = 1.0f / ws;

    acc += __shfl_down_sync(0xffffffffu, acc, 16);
    if (lane < 16) out[(size_t)gw * NCLS + c] = acc * rs + b2[c];
}

// ---------------- launch ----------------
extern "C" void kernel_launch(void* const* d_in, const int* in_sizes, int n_in,
                              void* d_out, int out_size) {
    const float* x    = (const float*)d_in[0];
    const void*  ei   = d_in[1];
    const float* W1   = (const float*)d_in[2];
    const float* as1w = (const float*)d_in[3];
    const float* ad1w = (const float*)d_in[4];
    const float* b1   = (const float*)d_in[5];
    const float* W2   = (const float*)d_in[6];
    const float* as2w = (const float*)d_in[7];
    const float* ad2w = (const float*)d_in[8];
    const float* b2   = (const float*)d_in[9];
    float* out = (float*)d_out;

    cudaFuncSetAttribute(gemm1_k, cudaFuncAttributeMaxDynamicSharedMemorySize, G1_SMEM);

    probe_k<<<1, 256>>>(ei);
    initcnt_k<<<(N_NODES + 255) / 256, 256>>>();
    count_k<<<(N_EDGES / 2 + 255) / 256, 256>>>(ei);
    // launch index 3 -> ncu capture slot
    gemm1_k<<<(N_NODES + MT - 1) / MT, 256, G1_SMEM>>>(x, W1, as1w, ad1w);

    scan1_k<<<NB1024, 1024>>>();
    scan2_k<<<1, 128>>>();
    scan3_selfloop_k<<<NB1024, 1024>>>();
    scatter_k<<<(N_EDGES / 2 + 255) / 256, 256>>>(ei);

    agg1_k<<<(N_NODES + 7) / 8, 256>>>(b1);
    gemm2_attn_k<<<(N_NODES + 15) / 16, 256>>>(W2, as2w, ad2w);
    agg2_k<<<(N_NODES + 7) / 8, 256>>>(b2, out);
}

// round 9
// speedup vs baseline: 1.2393x; 1.2393x over previous
#include <cuda_runtime.h>
#include <cuda_fp16.h>
#include <cstdint>

// ---------------- problem constants ----------------
#define N_NODES 100000
#define N_EDGES 3200000
#define F_IN    512
#define HEADS   8
#define HID     8
#define C1      64
#define NCLS    16
#define TOTE    (N_EDGES + N_NODES)
#define NB1024  ((N_NODES + 1023) / 1024)

// ---------------- device scratch ----------------
__device__ __half g_h1  [(size_t)N_NODES * C1];
__device__ float  g_hact[(size_t)N_NODES * C1];
__device__ float  g_as1 [(size_t)N_NODES * HEADS];
__device__ float  g_ad1 [(size_t)N_NODES * HEADS];
__device__ __half g_h2  [(size_t)N_NODES * NCLS];
__device__ float  g_as2 [N_NODES];
__device__ float  g_ad2 [N_NODES];
__device__ int    g_rowptr[N_NODES + 1];
__device__ int    g_cnt [N_NODES];
__device__ int    g_woff[N_NODES];
__device__ int    g_srcs[TOTE];
__device__ int    g_part [128];
__device__ int    g_part2[128];
__device__ int    g_is64;
__device__ unsigned g_gmax1[8];
__device__ unsigned g_gmax2;

// ---------------- helpers ----------------
__device__ __forceinline__ float leaky02(float x) { return fmaxf(x, 0.2f * x); }

__device__ __forceinline__ unsigned long long pack2(float x, float y) {
    unsigned long long r;
    asm("mov.b64 %0,{%1,%2};" : "=l"(r) : "f"(x), "f"(y));
    return r;
}
__device__ __forceinline__ void fma2(unsigned long long& d, unsigned long long a, unsigned long long b) {
    asm("fma.rn.f32x2 %0,%1,%2,%0;" : "+l"(d) : "l"(a), "l"(b));
}
__device__ __forceinline__ float2 unpack2(unsigned long long v) {
    float2 f;
    asm("mov.b64 {%0,%1},%2;" : "=f"(f.x), "=f"(f.y) : "l"(v));
    return f;
}
__device__ __forceinline__ unsigned fenc(float f) {
    unsigned u = __float_as_uint(f);
    return (u & 0x80000000u) ? ~u : (u | 0x80000000u);
}
__device__ __forceinline__ float fdec(unsigned u) {
    return __uint_as_float((u & 0x80000000u) ? (u & 0x7FFFFFFFu) : ~u);
}
#define ENC_NEG_INF 0x007FFFFFu

// ---------------- dtype probe + per-call resets ----------------
__global__ void probe_k(const void* ei) {
    __shared__ int s_bad;
    if (threadIdx.x < 8)  g_gmax1[threadIdx.x] = ENC_NEG_INF;
    if (threadIdx.x == 8) g_gmax2 = ENC_NEG_INF;
    if (threadIdx.x == 0) s_bad = 0;
    __syncthreads();
    const long long* p = (const long long*)ei;
    for (int i = threadIdx.x; i < 1024; i += blockDim.x) {
        long long v = p[i];
        if ((v >> 32) != 0) s_bad = 1;
    }
    __syncthreads();
    if (threadIdx.x == 0) g_is64 = (s_bad == 0) ? 1 : 0;
}

// ---------------- GEMM1 + fused attn coefs + fused head-max (R7 proven core) ----------------
#define MT 256
#define BK 16

__device__ __forceinline__ void g1_load(const float* __restrict__ X, int m0, int k0,
                                        int lrow0, int lh, const float* __restrict__ W,
                                        int tid, float4 ra[2][2], float4& rb) {
#pragma unroll
    for (int s = 0; s < 2; s++) {
        int row = lrow0 + s * 128;
        int gm  = m0 + row;
        if (gm < N_NODES) {
            const float4* p = (const float4*)(X + (size_t)gm * F_IN + k0 + lh);
            ra[s][0] = p[0];
            ra[s][1] = p[1];
        } else {
            ra[s][0] = make_float4(0.f, 0.f, 0.f, 0.f);
            ra[s][1] = make_float4(0.f, 0.f, 0.f, 0.f);
        }
    }
    rb = *(const float4*)(W + (size_t)(k0 + (tid >> 4)) * 64 + (tid & 15) * 4);
}

__device__ __forceinline__ void g1_store(float As[BK][MT], float Bs[BK][64],
                                         int lrow0, int lh, int tid,
                                         const float4 ra[2][2], const float4& rb) {
#pragma unroll
    for (int s = 0; s < 2; s++) {
        int row = lrow0 + s * 128;
        const float* f = (const float*)&ra[s][0];
#pragma unroll
        for (int j = 0; j < 8; j++) {
            int k = lh + j;
            As[k][row ^ ((2 * k) & 31)] = f[j];
        }
    }
    *(float4*)&Bs[tid >> 4][(tid & 15) * 4] = rb;
}

__global__ __launch_bounds__(256, 2) void gemm1_k(const float* __restrict__ X,
                                                  const float* __restrict__ W,
                                                  const float* __restrict__ asw,
                                                  const float* __restrict__ adw) {
    __shared__ float As[2][BK][MT];
    __shared__ float Bs[2][BK][64];
    __shared__ unsigned sMax[8];
    const int tid = threadIdx.x;
    const int m0  = blockIdx.x * MT;
    const int tx  = tid & 7;
    const int ty8 = (tid >> 3) * 8;
    const int lrow0 = tid >> 1;
    const int lh    = (tid & 1) * 8;
    if (tid < 8) sMax[tid] = ENC_NEG_INF;

    unsigned long long acc[4][8];
#pragma unroll
    for (int p = 0; p < 4; p++)
#pragma unroll
        for (int j = 0; j < 8; j++) acc[p][j] = 0ull;

    {
        float4 ra[2][2]; float4 rb;
        g1_load(X, m0, 0, lrow0, lh, W, tid, ra, rb);
        g1_store(As[0], Bs[0], lrow0, lh, tid, ra, rb);
    }
    __syncthreads();

    const int NT = F_IN / BK;
    for (int kt = 0; kt < NT; kt++) {
        const int cur = kt & 1;
        float4 ra[2][2]; float4 rb;
        const bool more = (kt + 1) < NT;
        if (more) g1_load(X, m0, (kt + 1) * BK, lrow0, lh, W, tid, ra, rb);

#pragma unroll
        for (int kk = 0; kk < BK; kk++) {
            const int swz = (2 * kk) & 31;
            unsigned long long a[4];
#pragma unroll
            for (int p = 0; p < 4; p++)
                a[p] = *(const unsigned long long*)&As[cur][kk][(ty8 + 2 * p) ^ swz];
            float4 u0 = *(const float4*)&Bs[cur][kk][tx * 8];
            float4 u1 = *(const float4*)&Bs[cur][kk][tx * 8 + 4];
            const float bj[8] = {u0.x, u0.y, u0.z, u0.w, u1.x, u1.y, u1.z, u1.w};
#pragma unroll
            for (int j = 0; j < 8; j++) {
                unsigned long long bb = pack2(bj[j], bj[j]);
#pragma unroll
                for (int p = 0; p < 4; p++) fma2(acc[p][j], a[p], bb);
            }
        }
        if (more) g1_store(As[cur ^ 1], Bs[cur ^ 1], lrow0, lh, tid, ra, rb);
        __syncthreads();
    }

    float sa[8], da[8];
#pragma unroll
    for (int j = 0; j < 8; j++) {
        sa[j] = __ldg(asw + tx * 8 + j);
        da[j] = __ldg(adw + tx * 8 + j);
    }
    float lmax = -1e30f;
#pragma unroll
    for (int p = 0; p < 4; p++) {
        float2 f[8];
#pragma unroll
        for (int j = 0; j < 8; j++) f[j] = unpack2(acc[p][j]);
#pragma unroll
        for (int e = 0; e < 2; e++) {
            int gm = m0 + ty8 + 2 * p + e;
            if (gm < N_NODES) {
                float o[8];
#pragma unroll
                for (int j = 0; j < 8; j++) o[j] = e ? f[j].y : f[j].x;
                union { __half2 h[4]; float4 f4; } u;
#pragma unroll
                for (int q = 0; q < 4; q++)
                    u.h[q] = __floats2half2_rn(o[2 * q], o[2 * q + 1]);
                *(float4*)(g_h1 + (size_t)gm * C1 + tx * 8) = u.f4;
                float sv = 0.f, dv = 0.f;
#pragma unroll
                for (int j = 0; j < 8; j++) { sv += o[j] * sa[j]; dv += o[j] * da[j]; }
                g_as1[(size_t)gm * 8 + tx] = sv;
                g_ad1[(size_t)gm * 8 + tx] = dv;
                lmax = fmaxf(lmax, sv);
            }
        }
    }
    atomicMax(&sMax[tx], fenc(lmax));
    __syncthreads();
    if (tid < 8) atomicMax(&g_gmax1[tid], sMax[tid]);
}

// ---------------- CSR build ----------------
__global__ void initcnt_k() {
    int n = blockIdx.x * blockDim.x + threadIdx.x;
    if (n < N_NODES) g_cnt[n] = 1;
}

__global__ void count_k(const void* ei) {   // 2 edges per thread
    long long e = 2 * ((long long)blockIdx.x * blockDim.x + threadIdx.x);
    if (e >= N_EDGES) return;
    int d0, d1;
    if (g_is64) {
        longlong2 v = *(const longlong2*)((const long long*)ei + N_EDGES + e);
        d0 = (int)v.x; d1 = (int)v.y;
    } else {
        int2 v = *(const int2*)((const int*)ei + N_EDGES + e);
        d0 = v.x; d1 = v.y;
    }
    atomicAdd(&g_cnt[d0], 1);
    atomicAdd(&g_cnt[d1], 1);
}

__global__ void scan1_k() {
    __shared__ int ws[32];
    const int b = blockIdx.x, t = threadIdx.x;
    const int i = b * 1024 + t;
    int v = (i < N_NODES) ? g_cnt[i] : 0;
    const int lane = t & 31, w = t >> 5;
    int x = v;
#pragma unroll
    for (int o = 1; o < 32; o <<= 1) {
        int y = __shfl_up_sync(0xffffffffu, x, o);
        if (lane >= o) x += y;
    }
    if (lane == 31) ws[w] = x;
    __syncthreads();
    if (w == 0) {
        int y = ws[lane];
#pragma unroll
        for (int o = 1; o < 32; o <<= 1) {
            int z = __shfl_up_sync(0xffffffffu, y, o);
            if (lane >= o) y += z;
        }
        ws[lane] = y;
    }
    __syncthreads();
    int off  = (w > 0) ? ws[w - 1] : 0;
    int incl = x + off;
    if (i < N_NODES) g_rowptr[i] = incl - v;
    if (t == 1023) g_part[b] = incl;
}

__global__ void scan2_k() {
    __shared__ int buf[128];
    int t = threadIdx.x;
    buf[t] = (t < NB1024) ? g_part[t] : 0;
    __syncthreads();
#pragma unroll
    for (int o = 1; o < 128; o <<= 1) {
        int y = (t >= o) ? buf[t - o] : 0;
        __syncthreads();
        buf[t] += y;
        __syncthreads();
    }
    g_part2[t] = buf[t];
}

__global__ void scan3_selfloop_k() {
    int b = blockIdx.x, i = b * 1024 + threadIdx.x;
    if (i == 0) g_rowptr[N_NODES] = TOTE;
    if (i >= N_NODES) return;
    int off = (b > 0) ? g_part2[b - 1] : 0;
    int p = g_rowptr[i] + off;
    g_rowptr[i] = p;
    g_srcs[p]   = i;
    g_woff[i]   = p + 1;
}

__global__ void scatter_k(const void* ei) {   // 2 edges per thread
    long long e = 2 * ((long long)blockIdx.x * blockDim.x + threadIdx.x);
    if (e >= N_EDGES) return;
    int s0, s1, d0, d1;
    if (g_is64) {
        longlong2 sv = *(const longlong2*)((const long long*)ei + e);
        longlong2 dv = *(const longlong2*)((const long long*)ei + N_EDGES + e);
        s0 = (int)sv.x; s1 = (int)sv.y; d0 = (int)dv.x; d1 = (int)dv.y;
    } else {
        int2 sv = *(const int2*)((const int*)ei + e);
        int2 dv = *(const int2*)((const int*)ei + N_EDGES + e);
        s0 = sv.x; s1 = sv.y; d0 = dv.x; d1 = dv.y;
    }
    int p0 = atomicAdd(&g_woff[d0], 1);
    g_srcs[p0] = s0;
    int p1 = atomicAdd(&g_woff[d1], 1);
    g_srcs[p1] = s1;
}

// ---------------- layer1 aggregate: single pass, half-warp-per-edge gather ----------------
__global__ void agg1_k(const float* __restrict__ b1) {
    const int gw   = (blockIdx.x * blockDim.x + threadIdx.x) >> 5;
    const int lane = threadIdx.x & 31;
    const int w    = threadIdx.x >> 5;
    __shared__ float sAl [8][8][32];
    __shared__ int   sSrc[8][32];
    if (gw >= N_NODES) return;
    const int beg = g_rowptr[gw], end = g_rowptr[gw + 1];

    float ad[8], mh[8];
    {
        float4 u = *(const float4*)(g_ad1 + (size_t)gw * 8);
        float4 v = *(const float4*)(g_ad1 + (size_t)gw * 8 + 4);
        ad[0]=u.x; ad[1]=u.y; ad[2]=u.z; ad[3]=u.w;
        ad[4]=v.x; ad[5]=v.y; ad[6]=v.z; ad[7]=v.w;
    }
#pragma unroll
    for (int h = 0; h < 8; h++)
        mh[h] = leaky02(fdec(g_gmax1[h]) + ad[h]);

    const int eh  = lane >> 4;
    const int li  = lane & 15;
    const int c0  = li * 4;
    const int hd2 = li >> 1;
    float ws[8];
#pragma unroll
    for (int h = 0; h < 8; h++) ws[h] = 0.f;
    float a0 = 0.f, a1 = 0.f, a2 = 0.f, a3 = 0.f;

    for (int chunk = beg; chunk < end; chunk += 32) {
        int i = chunk + lane;
        int sx = gw;
        float e8[8];
        if (i < end) {
            sx = g_srcs[i];
            float4 u = *(const float4*)(g_as1 + (size_t)sx * 8);
            float4 v = *(const float4*)(g_as1 + (size_t)sx * 8 + 4);
            float xs[8] = {u.x, u.y, u.z, u.w, v.x, v.y, v.z, v.w};
#pragma unroll
            for (int h = 0; h < 8; h++) {
                e8[h] = __expf(leaky02(xs[h] + ad[h]) - mh[h]);
                ws[h] += e8[h];
            }
        } else {
#pragma unroll
            for (int h = 0; h < 8; h++) e8[h] = 0.f;
        }
        sSrc[w][lane] = sx;
#pragma unroll
        for (int h = 0; h < 8; h++) sAl[w][h][lane] = e8[h];
        __syncwarp();

        const int ec = min(32, end - chunk);
        for (int e0 = 0; e0 < ec; e0 += 2) {
            const int edge = e0 + eh;
            const int   sy = sSrc[w][edge];
            const float al = sAl[w][hd2][edge];
            uint2 hv = *(const uint2*)(g_h1 + (size_t)sy * C1 + c0);
            float2 p0 = __half22float2(*(const __half2*)&hv.x);
            float2 p1 = __half22float2(*(const __half2*)&hv.y);
            a0 += p0.x * al; a1 += p0.y * al;
            a2 += p1.x * al; a3 += p1.y * al;
        }
        __syncwarp();
    }

#pragma unroll
    for (int o = 16; o; o >>= 1)
#pragma unroll
        for (int h = 0; h < 8; h++)
            ws[h] += __shfl_xor_sync(0xffffffffu, ws[h], o);

    a0 += __shfl_xor_sync(0xffffffffu, a0, 16);
    a1 += __shfl_xor_sync(0xffffffffu, a1, 16);
    a2 += __shfl_xor_sync(0xffffffffu, a2, 16);
    a3 += __shfl_xor_sync(0xffffffffu, a3, 16);

    if (lane < 16) {
        const float rsh = 1.0f / ws[hd2];
        float4 bb = *(const float4*)(b1 + c0);
        float o0 = a0 * rsh + bb.x;
        float o1 = a1 * rsh + bb.y;
        float o2 = a2 * rsh + bb.z;
        float o3 = a3 * rsh + bb.w;
        o0 = (o0 > 0.f) ? o0 : (__expf(o0) - 1.0f);
        o1 = (o1 > 0.f) ? o1 : (__expf(o1) - 1.0f);
        o2 = (o2 > 0.f) ? o2 : (__expf(o2) - 1.0f);
        o3 = (o3 > 0.f) ? o3 : (__expf(o3) - 1.0f);
        *(float4*)(g_hact + (size_t)gw * C1 + c0) = make_float4(o0, o1, o2, o3);
    }
}

// ---------------- layer2 GEMM + attn coefs + fused max ----------------
__global__ void gemm2_attn_k(const float* __restrict__ W2,
                             const float* __restrict__ asrc2,
                             const float* __restrict__ adst2) {
    __shared__ float Xs[16 * 64];
    __shared__ float Ws[64 * 16];
    __shared__ unsigned sM2;
    const int tid = threadIdx.x;
    const int n0  = blockIdx.x * 16;
    if (tid == 0) sM2 = ENC_NEG_INF;

    ((float4*)Ws)[tid] = ((const float4*)W2)[tid];
    {
        int row = tid >> 4;
        float4 v = make_float4(0.f, 0.f, 0.f, 0.f);
        if (n0 + row < N_NODES)
            v = ((const float4*)(g_hact + (size_t)n0 * C1))[tid];
        ((float4*)Xs)[tid] = v;
    }
    __syncthreads();

    const int r = tid >> 4, c = tid & 15;
    float acc = 0.f;
#pragma unroll
    for (int k = 0; k < 64; k++) acc += Xs[r * 64 + k] * Ws[k * 16 + c];
    const int n = n0 + r;
    if (n < N_NODES) g_h2[(size_t)n * NCLS + c] = __float2half_rn(acc);

    float vs = acc * asrc2[c];
    float vd = acc * adst2[c];
#pragma unroll
    for (int off = 8; off; off >>= 1) {
        vs += __shfl_xor_sync(0xffffffffu, vs, off);
        vd += __shfl_xor_sync(0xffffffffu, vd, off);
    }
    if (c == 0) {
        if (n < N_NODES) {
            g_as2[n] = vs;
            g_ad2[n] = vd;
            atomicMax(&sM2, fenc(vs));
        }
    }
    __syncthreads();
    if (tid == 0) atomicMax(&g_gmax2, sM2);
}

// ---------------- layer2 aggregate: single pass ----------------
__global__ void agg2_k(const float* __restrict__ b2, float* __restrict__ out) {
    const int gw   = (blockIdx.x * blockDim.x + threadIdx.x) >> 5;
    const int lane = threadIdx.x & 31;
    const int w    = threadIdx.x >> 5;
    __shared__ float sAl [8][32];
    __shared__ int   sSrc[8][32];
    if (gw >= N_NODES) return;
    const int beg = g_rowptr[gw], end = g_rowptr[gw + 1];
    const float adn = g_ad2[gw];
    const float mh  = leaky02(fdec(g_gmax2) + adn);

    const int c    = lane & 15;
    const int half = lane >> 4;
    float acc = 0.f, ws = 0.f;

    for (int chunk = beg; chunk < end; chunk += 32) {
        int i = chunk + lane;
        int sx = gw;
        float e = 0.f;
        if (i < end) {
            sx = g_srcs[i];
            e  = __expf(leaky02(g_as2[sx] + adn) - mh);
            ws += e;
        }
        sSrc[w][lane] = sx;
        sAl [w][lane] = e;
        __syncwarp();

        const int ec = min(32, end - chunk);
#pragma unroll 8
        for (int e0 = half; e0 < ec; e0 += 2) {
            int   sy = sSrc[w][e0];
            float al = sAl[w][e0];
            acc += __half2float(g_h2[(size_t)sy * NCLS + c]) * al;
        }
        __syncwarp();
    }

#pragma unroll
    for (int o = 16; o; o >>= 1)
        ws += __shfl_xor_sync(0xffffffffu, ws, o);
    const float rs = 1.0f / ws;

    acc += __shfl_down_sync(0xffffffffu, acc, 16);
    if (lane < 16) out[(size_t)gw * NCLS + c] = acc * rs + b2[c];
}

// ---------------- streams for graph fork/join (created at load, before checkpoints) ----------------
static cudaStream_t g_s1;
static cudaEvent_t  g_ev0, g_ev1;
namespace {
struct StreamInit {
    StreamInit() {
        cudaStreamCreateWithFlags(&g_s1, cudaStreamNonBlocking);
        cudaEventCreateWithFlags(&g_ev0, cudaEventDisableTiming);
        cudaEventCreateWithFlags(&g_ev1, cudaEventDisableTiming);
    }
};
static StreamInit g_streaminit;
}

// ---------------- launch ----------------
extern "C" void kernel_launch(void* const* d_in, const int* in_sizes, int n_in,
                              void* d_out, int out_size) {
    const float* x    = (const float*)d_in[0];
    const void*  ei   = d_in[1];
    const float* W1   = (const float*)d_in[2];
    const float* as1w = (const float*)d_in[3];
    const float* ad1w = (const float*)d_in[4];
    const float* b1   = (const float*)d_in[5];
    const float* W2   = (const float*)d_in[6];
    const float* as2w = (const float*)d_in[7];
    const float* ad2w = (const float*)d_in[8];
    const float* b2   = (const float*)d_in[9];
    float* out = (float*)d_out;

    probe_k<<<1, 256>>>(ei);

    // fork: CSR build on g_s1 runs concurrently with gemm1 on the main stream
    cudaEventRecord(g_ev0, 0);
    cudaStreamWaitEvent(g_s1, g_ev0, 0);

    initcnt_k<<<(N_NODES + 255) / 256, 256, 0, g_s1>>>();
    count_k<<<(N_EDGES / 2 + 255) / 256, 256, 0, g_s1>>>(ei);
    scan1_k<<<NB1024, 1024, 0, g_s1>>>();
    scan2_k<<<1, 128, 0, g_s1>>>();
    scan3_selfloop_k<<<NB1024, 1024, 0, g_s1>>>();
    scatter_k<<<(N_EDGES / 2 + 255) / 256, 256, 0, g_s1>>>(ei);
    cudaEventRecord(g_ev1, g_s1);

    gemm1_k<<<(N_NODES + MT - 1) / MT, 256>>>(x, W1, as1w, ad1w);

    // join: aggregates need both gemm1 outputs and the CSR
    cudaStreamWaitEvent(0, g_ev1, 0);

    agg1_k<<<(N_NODES + 7) / 8, 256>>>(b1);
    gemm2_attn_k<<<(N_NODES + 15) / 16, 256>>>(W2, as2w, ad2w);
    agg2_k<<<(N_NODES + 7) / 8, 256>>>(b2, out);
}